// round 1
// baseline (speedup 1.0000x reference)
#include <cuda_runtime.h>
#include <math.h>

// Problem dims (fixed by the dataset)
#define QD 256    // queries
#define II 2048   // gallery images
#define DD 256    // feature dim

// Main-kernel tiling
#define BQ 64
#define BI 64
#define KC 32
#define SROW 68   // smem row stride in floats: 68*4=272B, multiple of 16 -> float4 aligned, conflict-free

// ---- scratch (__device__ globals; no allocation allowed) ----
__device__ float d_CT[DD * QD];   // C = fqn*A, transposed [D][Q]
__device__ float d_AT[DD * QD];   // A = gate*inv_std, transposed [D][Q]
__device__ float d_GT[DD * II];   // normalized gallery, transposed [D][I]
__device__ float d_Bv[DD];        // B[d] = beta - mean*inv_std  (q-independent)
__device__ float d_c0[QD];        // c0[q] = sum_d fqn*B
__device__ float d_b0;            // b0 = sum_d B^2

// ---------------- block reduction (256 threads) ----------------
__device__ __forceinline__ float blockReduce256(float v) {
    __shared__ float sred[9];
    #pragma unroll
    for (int o = 16; o; o >>= 1) v += __shfl_xor_sync(0xffffffffu, v, o);
    if ((threadIdx.x & 31) == 0) sred[threadIdx.x >> 5] = v;
    __syncthreads();
    if (threadIdx.x == 0) {
        float s = 0.f;
        #pragma unroll
        for (int j = 0; j < 8; j++) s += sred[j];
        sred[8] = s;
    }
    __syncthreads();
    float r = sred[8];
    __syncthreads();
    return r;
}

// ---------------- per-query precompute: 256 blocks x 256 threads ----------------
__global__ void prep_q_kernel(const float* __restrict__ qf,
                              const float* __restrict__ qi,
                              const float* __restrict__ gamma,
                              const float* __restrict__ beta,
                              const float* __restrict__ mean,
                              const float* __restrict__ var) {
    int q = blockIdx.x;
    int d = threadIdx.x;

    float x = qf[q * DD + d];
    float xs = blockReduce256(x * x);
    float xn = x / fmaxf(sqrtf(xs), 1e-12f);
    float gate = 1.f / (1.f + expf(-xn * 5.0f));   // sigmoid(xn / 0.2)

    float istd = gamma[d] / sqrtf(var[d] + 1e-5f);
    float A = gate * istd;
    float B = beta[d] - mean[d] * istd;

    float y = qi[q * DD + d];
    float ys = blockReduce256(y * y);
    float yn = y / fmaxf(sqrtf(ys), 1e-12f);

    float fq = yn * A + B;                          // bn(yq*gate)
    float fs = blockReduce256(fq * fq);
    float fqn = fq / fmaxf(sqrtf(fs), 1e-12f);

    d_CT[d * QD + q] = fqn * A;
    d_AT[d * QD + q] = A;

    float c0 = blockReduce256(fqn * B);
    if (d == 0) d_c0[q] = c0;

    if (q == 0) {
        d_Bv[d] = B;
        float b0 = blockReduce256(B * B);
        if (d == 0) d_b0 = b0;
    }
}

// ---------------- per-gallery precompute: 2048 blocks x 256 threads ----------------
__global__ void prep_g_kernel(const float* __restrict__ gal) {
    int i = blockIdx.x;
    int d = threadIdx.x;
    float x = gal[i * DD + d];
    float ss = blockReduce256(x * x);
    d_GT[d * II + i] = x / fmaxf(sqrtf(ss), 1e-12f);
}

// ---------------- main scoring kernel ----------------
// grid (II/BI, QD/BQ) = (32, 4), block 256
__global__ __launch_bounds__(256) void score_kernel(float* __restrict__ out) {
    __shared__ float sC[KC][SROW];
    __shared__ float sA[KC][SROW];
    __shared__ float sG[KC][SROW];
    __shared__ float sB[KC];

    const int tid = threadIdx.x;
    const int tx = tid & 15;   // i direction
    const int ty = tid >> 4;   // q direction
    const int i0 = blockIdx.x * BI;
    const int q0 = blockIdx.y * BQ;

    float s1[4][4];
    float s2[4][4];
    #pragma unroll
    for (int u = 0; u < 4; u++)
        #pragma unroll
        for (int v = 0; v < 4; v++) { s1[u][v] = 0.f; s2[u][v] = 0.f; }

    for (int k0 = 0; k0 < DD; k0 += KC) {
        __syncthreads();
        // tile loads: 512 float4 per array; each thread loads 2 per array
        {
            int p = tid;
            #pragma unroll
            for (int it = 0; it < 2; it++, p += 256) {
                int qv = p & 15;    // float4 column
                int kc = p >> 4;    // 0..31
                float4 c4 = *(const float4*)&d_CT[(k0 + kc) * QD + q0 + qv * 4];
                *(float4*)&sC[kc][qv * 4] = c4;
                float4 a4 = *(const float4*)&d_AT[(k0 + kc) * QD + q0 + qv * 4];
                *(float4*)&sA[kc][qv * 4] = a4;
                float4 g4 = *(const float4*)&d_GT[(k0 + kc) * II + i0 + qv * 4];
                *(float4*)&sG[kc][qv * 4] = g4;
            }
            if (tid < KC) sB[tid] = d_Bv[k0 + tid];
        }
        __syncthreads();

        #pragma unroll
        for (int kc = 0; kc < KC; kc++) {
            float Bk = sB[kc];
            float4 c4 = *(const float4*)&sC[kc][ty * 4];
            float4 a4 = *(const float4*)&sA[kc][ty * 4];
            float4 g4 = *(const float4*)&sG[kc][tx * 4];
            float Cq[4] = {c4.x, c4.y, c4.z, c4.w};
            float Aq[4] = {a4.x, a4.y, a4.z, a4.w};
            float gi[4] = {g4.x, g4.y, g4.z, g4.w};
            float g2[4];
            #pragma unroll
            for (int v = 0; v < 4; v++) g2[v] = gi[v] * gi[v];
            #pragma unroll
            for (int u = 0; u < 4; u++) {
                float A2u = Aq[u] * Aq[u];
                float ABu = 2.f * Aq[u] * Bk;
                #pragma unroll
                for (int v = 0; v < 4; v++) {
                    s1[u][v] = fmaf(Cq[u], gi[v], s1[u][v]);
                    s2[u][v] = fmaf(A2u, g2[v], s2[u][v]);
                    s2[u][v] = fmaf(ABu, gi[v], s2[u][v]);
                }
            }
        }
    }

    // epilogue: score = sigmoid((s1+c0) / max(sqrt(s2+b0), 1e-12))
    float b0 = d_b0;
    #pragma unroll
    for (int u = 0; u < 4; u++) {
        int q = q0 + ty * 4 + u;
        float c0 = d_c0[q];
        float4 r;
        float* rp = &r.x;
        #pragma unroll
        for (int v = 0; v < 4; v++) {
            float denom = fmaxf(sqrtf(s2[u][v] + b0), 1e-12f);
            float val = (s1[u][v] + c0) / denom;
            rp[v] = 1.f / (1.f + expf(-val));
        }
        *(float4*)&out[q * II + i0 + tx * 4] = r;
    }
}

extern "C" void kernel_launch(void* const* d_in, const int* in_sizes, int n_in,
                              void* d_out, int out_size) {
    const float* query_feats      = (const float*)d_in[0];
    const float* query_img_feats  = (const float*)d_in[1];
    const float* gallery_img_feats= (const float*)d_in[2];
    const float* bn_gamma         = (const float*)d_in[3];
    const float* bn_beta          = (const float*)d_in[4];
    const float* bn_mean          = (const float*)d_in[5];
    const float* bn_var           = (const float*)d_in[6];
    float* out = (float*)d_out;

    prep_q_kernel<<<QD, 256>>>(query_feats, query_img_feats,
                               bn_gamma, bn_beta, bn_mean, bn_var);
    prep_g_kernel<<<II, 256>>>(gallery_img_feats);
    dim3 grid(II / BI, QD / BQ);
    score_kernel<<<grid, 256>>>(out);
}

// round 2
// speedup vs baseline: 1.0109x; 1.0109x over previous
#include <cuda_runtime.h>
#include <math.h>

// Problem dims (fixed by the dataset)
#define QD 256    // queries
#define II 2048   // gallery images
#define DD 256    // feature dim

// Main-kernel tiling
#define BQ 64
#define BI 64
#define KC 32
#define SROW 68   // smem row stride in floats (272B, float4-aligned, conflict-free)

typedef unsigned long long u64;

// ---- scratch (__device__ globals; no allocation allowed) ----
__device__ float d_CT [DD * QD];  // C   = fqn*A        transposed [D][Q]
__device__ float d_A2T[DD * QD];  // A^2                transposed [D][Q]
__device__ float d_ABT[DD * QD];  // 2*A*B              transposed [D][Q]
__device__ float d_GT [DD * II];  // normalized gallery transposed [D][I]
__device__ float d_c0 [QD];       // c0[q] = sum_d fqn*B
__device__ float d_b0;            // b0 = sum_d B^2

// ---------------- packed f32x2 helpers ----------------
__device__ __forceinline__ u64 pack2(float lo, float hi) {
    u64 r;
    asm("mov.b64 %0, {%1, %2};" : "=l"(r) : "f"(lo), "f"(hi));
    return r;
}
__device__ __forceinline__ void unpack2(u64 v, float& lo, float& hi) {
    asm("mov.b64 {%0, %1}, %2;" : "=f"(lo), "=f"(hi) : "l"(v));
}
__device__ __forceinline__ u64 mul2(u64 a, u64 b) {
    u64 r;
    asm("mul.rn.f32x2 %0, %1, %2;" : "=l"(r) : "l"(a), "l"(b));
    return r;
}
#define FMA2(acc, a, b) \
    asm("fma.rn.f32x2 %0, %1, %2, %0;" : "+l"(acc) : "l"(a), "l"(b))

// ---------------- warp reduction ----------------
__device__ __forceinline__ float warpSum(float v) {
    #pragma unroll
    for (int o = 16; o; o >>= 1) v += __shfl_xor_sync(0xffffffffu, v, o);
    return v;
}

// ---------------- per-query precompute: warp per query ----------------
// grid 32 x 256 threads = 256 warps = 256 queries; lane handles 8 d's
__global__ void prep_q_kernel(const float* __restrict__ qf,
                              const float* __restrict__ qi,
                              const float* __restrict__ gamma,
                              const float* __restrict__ beta,
                              const float* __restrict__ mean,
                              const float* __restrict__ var) {
    const int q    = (blockIdx.x * blockDim.x + threadIdx.x) >> 5;
    const int lane = threadIdx.x & 31;

    float x[8], y[8], istd[8], B[8];
    float xs = 0.f, ys = 0.f;
    #pragma unroll
    for (int j = 0; j < 8; j++) {
        int d = lane + 32 * j;
        x[j] = qf[q * DD + d];
        y[j] = qi[q * DD + d];
        istd[j] = gamma[d] * rsqrtf(var[d] + 1e-5f);
        B[j] = beta[d] - mean[d] * istd[j];
        xs += x[j] * x[j];
        ys += y[j] * y[j];
    }
    xs = warpSum(xs);
    ys = warpSum(ys);
    float xin = 1.f / fmaxf(sqrtf(xs), 1e-12f);
    float yin = 1.f / fmaxf(sqrtf(ys), 1e-12f);

    float A[8], fq[8];
    float fs = 0.f;
    #pragma unroll
    for (int j = 0; j < 8; j++) {
        float xn = x[j] * xin;
        float gate = 1.f / (1.f + __expf(-xn * 5.0f));  // sigmoid(xn/0.2)
        A[j] = gate * istd[j];
        float yn = y[j] * yin;
        fq[j] = yn * A[j] + B[j];                        // bn(yq*gate)
        fs += fq[j] * fq[j];
    }
    fs = warpSum(fs);
    float fin = 1.f / fmaxf(sqrtf(fs), 1e-12f);

    float c0 = 0.f;
    #pragma unroll
    for (int j = 0; j < 8; j++) {
        int d = lane + 32 * j;
        float fqn = fq[j] * fin;
        d_CT [d * QD + q] = fqn * A[j];
        d_A2T[d * QD + q] = A[j] * A[j];
        d_ABT[d * QD + q] = 2.f * A[j] * B[j];
        c0 += fqn * B[j];
    }
    c0 = warpSum(c0);
    if (lane == 0) d_c0[q] = c0;

    if (q == 0) {
        float b0 = 0.f;
        #pragma unroll
        for (int j = 0; j < 8; j++) b0 += B[j] * B[j];
        b0 = warpSum(b0);
        if (lane == 0) d_b0 = b0;
    }
}

// ---------------- per-gallery precompute: warp per row ----------------
// grid 256 x 256 = 2048 warps = 2048 rows
__global__ void prep_g_kernel(const float* __restrict__ gal) {
    const int i    = (blockIdx.x * blockDim.x + threadIdx.x) >> 5;
    const int lane = threadIdx.x & 31;

    float x[8];
    float ss = 0.f;
    #pragma unroll
    for (int j = 0; j < 8; j++) {
        x[j] = gal[i * DD + lane + 32 * j];
        ss += x[j] * x[j];
    }
    ss = warpSum(ss);
    float inv = 1.f / fmaxf(sqrtf(ss), 1e-12f);
    #pragma unroll
    for (int j = 0; j < 8; j++)
        d_GT[(lane + 32 * j) * II + i] = x[j] * inv;
}

// ---------------- main scoring kernel ----------------
// grid (II/BI, QD/BQ) = (32, 4), block 256
__global__ __launch_bounds__(256) void score_kernel(float* __restrict__ out) {
    __shared__ float sC [KC][SROW];
    __shared__ float sA2[KC][SROW];
    __shared__ float sAB[KC][SROW];
    __shared__ float sG [KC][SROW];

    const int tid = threadIdx.x;
    const int tx = tid & 15;   // i direction (4 floats = 2 f32x2 pairs)
    const int ty = tid >> 4;   // q direction (4 floats)
    const int i0 = blockIdx.x * BI;
    const int q0 = blockIdx.y * BQ;

    u64 s1[4][2], s2[4][2];
    const u64 z = pack2(0.f, 0.f);
    #pragma unroll
    for (int u = 0; u < 4; u++) {
        s1[u][0] = z; s1[u][1] = z;
        s2[u][0] = z; s2[u][1] = z;
    }

    for (int k0 = 0; k0 < DD; k0 += KC) {
        __syncthreads();
        {
            int p = tid;
            #pragma unroll
            for (int it = 0; it < 2; it++, p += 256) {
                int qv = p & 15;    // float4 column
                int kc = p >> 4;    // 0..31
                *(float4*)&sC [kc][qv * 4] = *(const float4*)&d_CT [(k0 + kc) * QD + q0 + qv * 4];
                *(float4*)&sA2[kc][qv * 4] = *(const float4*)&d_A2T[(k0 + kc) * QD + q0 + qv * 4];
                *(float4*)&sAB[kc][qv * 4] = *(const float4*)&d_ABT[(k0 + kc) * QD + q0 + qv * 4];
                *(float4*)&sG [kc][qv * 4] = *(const float4*)&d_GT [(k0 + kc) * II + i0 + qv * 4];
            }
        }
        __syncthreads();

        #pragma unroll
        for (int kc = 0; kc < KC; kc++) {
            float4 g4  = *(const float4*)&sG [kc][tx * 4];
            float4 c4  = *(const float4*)&sC [kc][ty * 4];
            float4 a24 = *(const float4*)&sA2[kc][ty * 4];
            float4 ab4 = *(const float4*)&sAB[kc][ty * 4];

            u64 gp0 = pack2(g4.x, g4.y);
            u64 gp1 = pack2(g4.z, g4.w);
            u64 g2p0 = mul2(gp0, gp0);
            u64 g2p1 = mul2(gp1, gp1);

            float Cq[4]  = {c4.x,  c4.y,  c4.z,  c4.w};
            float A2q[4] = {a24.x, a24.y, a24.z, a24.w};
            float ABq[4] = {ab4.x, ab4.y, ab4.z, ab4.w};

            #pragma unroll
            for (int u = 0; u < 4; u++) {
                u64 cu  = pack2(Cq[u],  Cq[u]);
                u64 a2u = pack2(A2q[u], A2q[u]);
                u64 abu = pack2(ABq[u], ABq[u]);
                FMA2(s1[u][0], cu,  gp0);
                FMA2(s1[u][1], cu,  gp1);
                FMA2(s2[u][0], a2u, g2p0);
                FMA2(s2[u][1], a2u, g2p1);
                FMA2(s2[u][0], abu, gp0);
                FMA2(s2[u][1], abu, gp1);
            }
        }
    }

    // epilogue: score = sigmoid((s1+c0) / max(sqrt(s2+b0), 1e-12))
    const float b0 = d_b0;
    #pragma unroll
    for (int u = 0; u < 4; u++) {
        int q = q0 + ty * 4 + u;
        float c0 = d_c0[q];
        float a[4], b[4];
        unpack2(s1[u][0], a[0], a[1]);
        unpack2(s1[u][1], a[2], a[3]);
        unpack2(s2[u][0], b[0], b[1]);
        unpack2(s2[u][1], b[2], b[3]);
        float4 r;
        float* rp = &r.x;
        #pragma unroll
        for (int v = 0; v < 4; v++) {
            float denom = fmaxf(sqrtf(b[v] + b0), 1e-12f);
            float val = (a[v] + c0) / denom;
            rp[v] = 1.f / (1.f + __expf(-val));
        }
        *(float4*)&out[q * II + i0 + tx * 4] = r;
    }
}

extern "C" void kernel_launch(void* const* d_in, const int* in_sizes, int n_in,
                              void* d_out, int out_size) {
    const float* query_feats       = (const float*)d_in[0];
    const float* query_img_feats   = (const float*)d_in[1];
    const float* gallery_img_feats = (const float*)d_in[2];
    const float* bn_gamma          = (const float*)d_in[3];
    const float* bn_beta           = (const float*)d_in[4];
    const float* bn_mean           = (const float*)d_in[5];
    const float* bn_var            = (const float*)d_in[6];
    float* out = (float*)d_out;

    prep_q_kernel<<<32, 256>>>(query_feats, query_img_feats,
                               bn_gamma, bn_beta, bn_mean, bn_var);
    prep_g_kernel<<<256, 256>>>(gallery_img_feats);
    dim3 grid(II / BI, QD / BQ);
    score_kernel<<<grid, 256>>>(out);
}